// round 1
// baseline (speedup 1.0000x reference)
#include <cuda_runtime.h>

typedef unsigned long long ull;

#define BSZ    2
#define SEQ    2048
#define EMBED  1024
#define HEADS  16
#define HDIM   64
#define NTOK   (BSZ*SEQ)

// ---------------- scratch (no allocations allowed) ----------------
__device__ float g_Q[NTOK*EMBED];
__device__ float g_K[NTOK*EMBED];
__device__ float g_V[NTOK*EMBED];
__device__ float g_Ctx[NTOK*EMBED];

// ---------------- f32x2 helpers (dual-issue FP32 pipe) -------------
__device__ __forceinline__ void fma2(ull &c, ull a, ull b) {
    asm("fma.rn.f32x2 %0, %1, %2, %0;" : "+l"(c) : "l"(a), "l"(b));
}
__device__ __forceinline__ float2 upk(ull v) {
    float2 f; asm("mov.b64 {%0,%1}, %2;" : "=f"(f.x), "=f"(f.y) : "l"(v)); return f;
}
__device__ __forceinline__ ull pk(float x, float y) {
    ull r; asm("mov.b64 %0, {%1,%2};" : "=l"(r) : "f"(x), "f"(y)); return r;
}

// ===================================================================
// GEMM (NT):  C[M,N] = A[M,K] @ W[N,K]^T + bias[N]
// BM=128, BN=64, BK=16; 256 threads; 8x4 micro-tile; K-paired f32x2.
// ===================================================================
#define GBM 128
#define GBN 64
#define GBK 16
#define GST 18   // smem row stride (even for 8B align; 18*tc distinct mod 32)

__global__ __launch_bounds__(256)
void sgemm_nt_bias(const float* __restrict__ A, const float* __restrict__ W,
                   const float* __restrict__ bias, float* __restrict__ C,
                   int M, int N, int K)
{
    __shared__ __align__(16) float As[GBM*GST];
    __shared__ __align__(16) float Ws[GBN*GST];

    const int tid = threadIdx.x;
    const int bm  = blockIdx.y * GBM;
    const int bn  = blockIdx.x * GBN;
    const int tr  = tid >> 4;          // 0..15
    const int tc  = tid & 15;          // 0..15
    const int rbase = tr * 8;

    ull acc[8][4];
#pragma unroll
    for (int i = 0; i < 8; i++)
#pragma unroll
        for (int j = 0; j < 4; j++) acc[i][j] = 0ull;

    const int lr  = tid >> 2;          // 0..63
    const int lkc = (tid & 3) * 4;     // 0,4,8,12

    for (int k0 = 0; k0 < K; k0 += GBK) {
        // A tile: 128x16 (two rows' worth per thread)
#pragma unroll
        for (int i = 0; i < 2; i++) {
            int r = lr + i * 64;
            float4 v = *(const float4*)(A + (size_t)(bm + r) * K + k0 + lkc);
            float* dst = &As[r * GST + lkc];
            *(float2*)(dst)     = make_float2(v.x, v.y);
            *(float2*)(dst + 2) = make_float2(v.z, v.w);
        }
        // W tile: 64x16
        {
            float4 v = *(const float4*)(W + (size_t)(bn + lr) * K + k0 + lkc);
            float* dst = &Ws[lr * GST + lkc];
            *(float2*)(dst)     = make_float2(v.x, v.y);
            *(float2*)(dst + 2) = make_float2(v.z, v.w);
        }
        __syncthreads();

#pragma unroll
        for (int kp = 0; kp < GBK / 2; kp++) {
            ull a[8], b[4];
#pragma unroll
            for (int i = 0; i < 8; i++)
                a[i] = *(const ull*)&As[(rbase + i) * GST + 2 * kp];
#pragma unroll
            for (int j = 0; j < 4; j++)
                b[j] = *(const ull*)&Ws[(tc + j * 16) * GST + 2 * kp];
#pragma unroll
            for (int i = 0; i < 8; i++)
#pragma unroll
                for (int j = 0; j < 4; j++)
                    fma2(acc[i][j], a[i], b[j]);
        }
        __syncthreads();
    }

#pragma unroll
    for (int i = 0; i < 8; i++) {
        const int row = bm + rbase + i;
#pragma unroll
        for (int j = 0; j < 4; j++) {
            const int col = bn + tc + j * 16;
            float2 s = upk(acc[i][j]);
            C[(size_t)row * N + col] = s.x + s.y + bias[col];
        }
    }
}

// ===================================================================
// Causal flash attention, fp32. One block = 64 queries of one (b,h).
// 8 warps x 8 query rows. 64-key tiles, online softmax.
// ===================================================================
#define FS 68   // smem row stride: 16B-aligned, conflict-free f4 column reads

__global__ __launch_bounds__(256)
void flash_attn(const float* __restrict__ Q, const float* __restrict__ K,
                const float* __restrict__ V, float* __restrict__ O)
{
    extern __shared__ __align__(16) float smem[];
    float* Qs = smem;
    float* Ks = smem + 64 * FS;
    float* Vs = smem + 2 * 64 * FS;
    float* Ps = smem + 3 * 64 * FS;

    const int tid   = threadIdx.x;
    const int warp  = tid >> 5;
    const int lane  = tid & 31;
    const int qtile = blockIdx.x;
    const int h     = blockIdx.y;
    const int b     = blockIdx.z;
    const int q0    = qtile * 64;
    const int rbase = warp * 8;
    const size_t headoff = (size_t)h * HDIM;

    // load Q tile, pre-scaled by 1/sqrt(64)
#pragma unroll
    for (int i = 0; i < 4; i++) {
        int e = tid + i * 256;
        int r = e >> 4;
        int c = (e & 15) * 4;
        float4 v = *(const float4*)(Q + (size_t)(b * SEQ + q0 + r) * EMBED + headoff + c);
        v.x *= 0.125f; v.y *= 0.125f; v.z *= 0.125f; v.w *= 0.125f;
        *(float4*)&Qs[r * FS + c] = v;
    }

    float m[8], l[8], o0[8], o1[8];
#pragma unroll
    for (int rr = 0; rr < 8; rr++) { m[rr] = -1e30f; l[rr] = 0.0f; o0[rr] = 0.0f; o1[rr] = 0.0f; }

    for (int kt = 0; kt <= qtile; kt++) {
        __syncthreads();   // previous tile's Vs/Ks reads complete; Qs visible on iter 0
        const int kbase = kt * 64;
#pragma unroll
        for (int i = 0; i < 4; i++) {
            int e = tid + i * 256;
            int r = e >> 4;
            int c = (e & 15) * 4;
            size_t g = (size_t)(b * SEQ + kbase + r) * EMBED + headoff + c;
            *(float4*)&Ks[r * FS + c] = *(const float4*)(K + g);
            *(float4*)&Vs[r * FS + c] = *(const float4*)(V + g);
        }
        __syncthreads();

        // ---- S = Q K^T (each lane: keys `lane` and `lane+32`) ----
#pragma unroll
        for (int rr = 0; rr < 8; rr++) {
            const float* qrow = &Qs[(rbase + rr) * FS];
            const float* k0p  = &Ks[lane * FS];
            const float* k1p  = &Ks[(lane + 32) * FS];
            ull s0a = 0ull, s0b = 0ull, s1a = 0ull, s1b = 0ull;
#pragma unroll
            for (int d = 0; d < 64; d += 4) {
                float4 q  = *(const float4*)(qrow + d);
                float4 ka = *(const float4*)(k0p + d);
                float4 kb = *(const float4*)(k1p + d);
                ull qlo = pk(q.x, q.y), qhi = pk(q.z, q.w);
                fma2(s0a, qlo, pk(ka.x, ka.y));
                fma2(s0b, qhi, pk(ka.z, ka.w));
                fma2(s1a, qlo, pk(kb.x, kb.y));
                fma2(s1b, qhi, pk(kb.z, kb.w));
            }
            float2 u;
            u = upk(s0a); float s0 = u.x + u.y; u = upk(s0b); s0 += u.x + u.y;
            u = upk(s1a); float s1 = u.x + u.y; u = upk(s1b); s1 += u.x + u.y;

            const int qg = q0 + rbase + rr;
            if (kbase + lane      > qg) s0 = -1e30f;
            if (kbase + lane + 32 > qg) s1 = -1e30f;

            float mx = fmaxf(s0, s1);
#pragma unroll
            for (int off = 16; off > 0; off >>= 1)
                mx = fmaxf(mx, __shfl_xor_sync(0xffffffffu, mx, off));
            float mnew = fmaxf(m[rr], mx);
            float corr = __expf(m[rr] - mnew);
            float p0 = __expf(s0 - mnew);
            float p1 = __expf(s1 - mnew);
            float ps = p0 + p1;
#pragma unroll
            for (int off = 16; off > 0; off >>= 1)
                ps += __shfl_xor_sync(0xffffffffu, ps, off);
            l[rr] = l[rr] * corr + ps;
            o0[rr] *= corr; o1[rr] *= corr;
            m[rr] = mnew;
            Ps[(rbase + rr) * FS + lane]      = p0;
            Ps[(rbase + rr) * FS + lane + 32] = p1;
        }
        __syncwarp();

        // ---- O += P V  (each lane owns dims 2*lane, 2*lane+1) ----
#pragma unroll 4
        for (int c = 0; c < 64; c++) {
            float2 v = *(const float2*)&Vs[c * FS + 2 * lane];
#pragma unroll
            for (int rr = 0; rr < 8; rr++) {
                float p = Ps[(rbase + rr) * FS + c];
                o0[rr] += p * v.x;
                o1[rr] += p * v.y;
            }
        }
        __syncwarp();
    }

#pragma unroll
    for (int rr = 0; rr < 8; rr++) {
        float inv = 1.0f / l[rr];
        float2 o = make_float2(o0[rr] * inv, o1[rr] * inv);
        *(float2*)(O + (size_t)(b * SEQ + q0 + rbase + rr) * EMBED + headoff + 2 * lane) = o;
    }
}

// ===================================================================
// launcher
// ===================================================================
extern "C" void kernel_launch(void* const* d_in, const int* in_sizes, int n_in,
                              void* d_out, int out_size)
{
    (void)in_sizes; (void)n_in; (void)out_size;
    const float* query = (const float*)d_in[0];
    const float* key   = (const float*)d_in[1];
    const float* value = (const float*)d_in[2];
    // d_in[3] is the causal mask: analytically tril, applied in-kernel.
    const float* Wq = (const float*)d_in[4];
    const float* bq = (const float*)d_in[5];
    const float* Wk = (const float*)d_in[6];
    const float* bk = (const float*)d_in[7];
    const float* Wv = (const float*)d_in[8];
    const float* bv = (const float*)d_in[9];
    const float* Wo = (const float*)d_in[10];
    const float* bo = (const float*)d_in[11];
    float* out = (float*)d_out;

    float *pQ, *pK, *pV, *pC;
    cudaGetSymbolAddress((void**)&pQ, g_Q);
    cudaGetSymbolAddress((void**)&pK, g_K);
    cudaGetSymbolAddress((void**)&pV, g_V);
    cudaGetSymbolAddress((void**)&pC, g_Ctx);

    cudaFuncSetAttribute(flash_attn, cudaFuncAttributeMaxDynamicSharedMemorySize,
                         4 * 64 * FS * (int)sizeof(float));

    dim3 gp(EMBED / GBN, NTOK / GBM);     // (16, 32)
    sgemm_nt_bias<<<gp, 256>>>(query, Wq, bq, pQ, NTOK, EMBED, EMBED);
    sgemm_nt_bias<<<gp, 256>>>(key,   Wk, bk, pK, NTOK, EMBED, EMBED);
    sgemm_nt_bias<<<gp, 256>>>(value, Wv, bv, pV, NTOK, EMBED, EMBED);

    dim3 ga(SEQ / 64, HEADS, BSZ);
    flash_attn<<<ga, 256, 4 * 64 * FS * (int)sizeof(float)>>>(pQ, pK, pV, pC);

    sgemm_nt_bias<<<gp, 256>>>(pC, Wo, bo, out, NTOK, EMBED, EMBED);
}

// round 3
// speedup vs baseline: 1.7617x; 1.7617x over previous
#include <cuda_runtime.h>
#include <cuda.h>
#include <cuda_bf16.h>
#include <cstdint>

typedef unsigned long long ull;

#define BSZ    2
#define SEQ    2048
#define EMBED  1024
#define HEADS  16
#define HDIM   64
#define NTOK   (BSZ*SEQ)

// ---------------- scratch (no allocations allowed) ----------------
__device__ float g_Q[NTOK*EMBED];
__device__ float g_K[NTOK*EMBED];
__device__ float g_V[NTOK*EMBED];
__device__ float g_Ctx[NTOK*EMBED];
__device__ __nv_bfloat16 g_Ah[NTOK*EMBED];
__device__ __nv_bfloat16 g_Al[NTOK*EMBED];
__device__ __nv_bfloat16 g_Wh[EMBED*EMBED];
__device__ __nv_bfloat16 g_Wl[EMBED*EMBED];

// ---------------- small PTX helpers (all non-'a' features) ---------
__device__ __forceinline__ uint32_t smem_u32(const void* p) {
    uint32_t a;
    asm("{ .reg .u64 t; cvta.to.shared.u64 t, %1; cvt.u32.u64 %0, t; }" : "=r"(a) : "l"(p));
    return a;
}

#define MBARRIER_INIT(mbar, cnt) \
    asm volatile("mbarrier.init.shared.b64 [%0], %1;" :: "r"(mbar), "r"(cnt) : "memory")
#define MBARRIER_EXPECT_TX(mbar, bytes) \
    asm volatile("mbarrier.arrive.expect_tx.shared.b64 _, [%0], %1;" :: "r"(mbar), "r"(bytes) : "memory")
#define MBARRIER_ARRIVE(mbar) \
    asm volatile("mbarrier.arrive.release.cta.shared.b64 _, [%0];" :: "r"(mbar) : "memory")

#define MBARRIER_WAIT_PARITY(mbar_addr, phase_parity) do {                                   \
    uint32_t _mbar = (uint32_t)(mbar_addr);                                                  \
    uint32_t _par  = (uint32_t)(phase_parity);                                               \
    uint32_t _done;                                                                          \
    asm volatile("{\n\t.reg .pred p;\n\t"                                                    \
        "mbarrier.try_wait.parity.acquire.cta.shared::cta.b64 p, [%1], %2;\n\t"              \
        "selp.b32 %0, 1, 0, p;\n\t}"                                                         \
        : "=r"(_done) : "r"(_mbar), "r"(_par) : "memory");                                   \
    if (!_done) {                                                                            \
        asm volatile("{\n\t.reg .pred P1;\n\t"                                               \
            "WL_%=:\n\t"                                                                     \
            "mbarrier.try_wait.parity.acquire.cta.shared::cta.b64 P1, [%0], %1, 0x989680;\n\t" \
            "@P1 bra.uni WD_%=;\n\t"                                                         \
            "bra.uni WL_%=;\n\t"                                                             \
            "WD_%=:\n\t}"                                                                    \
            :: "r"(_mbar), "r"(_par) : "memory");                                            \
    }                                                                                        \
} while (0)

__device__ __forceinline__ void tma2d(uint32_t dst, const CUtensorMap* map,
                                      int x, int y, uint32_t mbar) {
    asm volatile(
        "cp.async.bulk.tensor.2d.shared::cta.global.tile.mbarrier::complete_tx::bytes "
        "[%0], [%1, {%2, %3}], [%4];"
        :: "r"(dst), "l"(map), "r"(x), "r"(y), "r"(mbar) : "memory");
}

// ldmatrix x4 (b16), non-transposed
#define LDSM4(r, addr)                                                           \
    asm volatile("ldmatrix.sync.aligned.m8n8.x4.shared.b16 {%0,%1,%2,%3}, [%4];" \
        : "=r"((r)[0]), "=r"((r)[1]), "=r"((r)[2]), "=r"((r)[3]) : "r"(addr))

// mma m16n8k16 bf16 -> f32 accumulate in place
#define MMA16816(d, a, b0v, b1v)                                                 \
    asm volatile("mma.sync.aligned.m16n8k16.row.col.f32.bf16.bf16.f32 "          \
        "{%0,%1,%2,%3}, {%4,%5,%6,%7}, {%8,%9}, {%0,%1,%2,%3};"                  \
        : "+f"((d)[0]), "+f"((d)[1]), "+f"((d)[2]), "+f"((d)[3])                 \
        : "r"((a)[0]), "r"((a)[1]), "r"((a)[2]), "r"((a)[3]), "r"(b0v), "r"(b1v))

__device__ __forceinline__ uint32_t swz128(uint32_t o) {  // Swizzle<3,4,3>
    return o ^ ((o >> 3) & 0x70u);
}

// ---------------- f32x2 helpers (flash) ----------------------------
__device__ __forceinline__ void fma2(ull &c, ull a, ull b) {
    asm("fma.rn.f32x2 %0, %1, %2, %0;" : "+l"(c) : "l"(a), "l"(b));
}
__device__ __forceinline__ float2 upk(ull v) {
    float2 f; asm("mov.b64 {%0,%1}, %2;" : "=f"(f.x), "=f"(f.y) : "l"(v)); return f;
}
__device__ __forceinline__ ull pk(float x, float y) {
    ull r; asm("mov.b64 %0, {%1,%2};" : "=l"(r) : "f"(x), "f"(y)); return r;
}

// ===================================================================
// split: fp32 -> bf16 hi + bf16 lo  (x == hi + lo to ~2^-17)
// ===================================================================
__global__ __launch_bounds__(256)
void split_bf16(const float* __restrict__ x, __nv_bfloat16* __restrict__ hi,
                __nv_bfloat16* __restrict__ lo)
{
    int i = (blockIdx.x * 256 + threadIdx.x) * 4;
    float4 v = *(const float4*)(x + i);
    __nv_bfloat16 h0 = __float2bfloat16_rn(v.x);
    __nv_bfloat16 h1 = __float2bfloat16_rn(v.y);
    __nv_bfloat16 h2 = __float2bfloat16_rn(v.z);
    __nv_bfloat16 h3 = __float2bfloat16_rn(v.w);
    __nv_bfloat16 l0 = __float2bfloat16_rn(v.x - __bfloat162float(h0));
    __nv_bfloat16 l1 = __float2bfloat16_rn(v.y - __bfloat162float(h1));
    __nv_bfloat16 l2 = __float2bfloat16_rn(v.z - __bfloat162float(h2));
    __nv_bfloat16 l3 = __float2bfloat16_rn(v.w - __bfloat162float(h3));
    ushort4 hv = make_ushort4(*(unsigned short*)&h0, *(unsigned short*)&h1,
                              *(unsigned short*)&h2, *(unsigned short*)&h3);
    ushort4 lv = make_ushort4(*(unsigned short*)&l0, *(unsigned short*)&l1,
                              *(unsigned short*)&l2, *(unsigned short*)&l3);
    *(ushort4*)(hi + i) = hv;
    *(ushort4*)(lo + i) = lv;
}

// ===================================================================
// bf16x3 GEMM (NT) via mma.sync: C[4096,1024] = A @ W^T + bias
// BM=128 BN=128 BK=64, 3-stage TMA ring, 256 threads (8 warps).
// Warp tile 32x64: 2(m16) x 8(n8) mma grid, 3 passes (hh, hl, lh).
// ===================================================================
#define GK      1024
#define GN      1024
#define GBK     64
#define GNK     (GK/GBK)          // 16
#define GS      3                 // stages
#define TILE_B  16384             // 128 rows x 128B
#define STAGE_B (4*TILE_B)        // Ah, Al, Wh, Wl
#define GEMM_SMEM (GS*STAGE_B + 1024)

__global__ __launch_bounds__(256)
void gemm_bf16x3(const __grid_constant__ CUtensorMap tmAh,
                 const __grid_constant__ CUtensorMap tmAl,
                 const __grid_constant__ CUtensorMap tmBh,
                 const __grid_constant__ CUtensorMap tmBl,
                 const float* __restrict__ bias, float* __restrict__ C)
{
    extern __shared__ uint8_t dsm[];
    __shared__ __align__(8) ull s_mbar[2 * GS];   // full[0..2], empty[0..2]

    const int tid  = threadIdx.x;
    const int wid  = tid >> 5;
    const int lane = tid & 31;
    const int wm   = wid & 3;     // 4 m-groups of 32 rows
    const int wn   = wid >> 2;    // 2 n-groups of 64 cols
    const int bm   = blockIdx.y * 128;
    const int bn   = blockIdx.x * 128;

    const uint32_t tile0 = (smem_u32(dsm) + 1023u) & ~1023u;
    const uint32_t mb    = smem_u32(s_mbar);
    const uint32_t full0 = mb;            // +8*s
    const uint32_t emt0  = mb + 8 * GS;   // +8*s

    if (tid == 0) {
        for (int s = 0; s < GS; s++) {
            MBARRIER_INIT(full0 + 8 * s, 1);
            MBARRIER_INIT(emt0 + 8 * s, 8);   // one arrive per warp
        }
    }
    __syncthreads();

    // ---- prologue: fill all 3 stages ----
    if (tid == 0) {
#pragma unroll
        for (int s = 0; s < GS; s++) {
            uint32_t st = tile0 + s * STAGE_B;
            MBARRIER_EXPECT_TX(full0 + 8 * s, STAGE_B);
            int k0 = s * GBK;
            tma2d(st,              &tmAh, k0, bm, full0 + 8 * s);
            tma2d(st + TILE_B,     &tmAl, k0, bm, full0 + 8 * s);
            tma2d(st + 2 * TILE_B, &tmBh, k0, bn, full0 + 8 * s);
            tma2d(st + 3 * TILE_B, &tmBl, k0, bn, full0 + 8 * s);
        }
    }

    float acc[2][8][4];
#pragma unroll
    for (int i = 0; i < 2; i++)
#pragma unroll
        for (int j = 0; j < 8; j++)
#pragma unroll
            for (int q = 0; q < 4; q++) acc[i][j][q] = 0.0f;

    // precomputed lane offsets (tile-relative, before stage base)
    const int aRow = wm * 32 + (lane & 7) + ((lane >> 3) & 1) * 8;  // + sub*16
    const uint32_t aOffBase = (uint32_t)aRow * 128 + ((lane >> 4) & 1) * 16;
    const int bRow = wn * 64 + (lane & 7) + ((lane >> 4) & 1) * 8;  // + nb*16
    const uint32_t bOffBase = (uint32_t)bRow * 128 + ((lane >> 3) & 1) * 16;

    for (int i = 0; i < GNK; i++) {
        const int s  = i % GS;
        const int ph = (i / GS) & 1;
        MBARRIER_WAIT_PARITY(full0 + 8 * s, ph);

        const uint32_t st  = tile0 + s * STAGE_B;
        const uint32_t aH = st, aL = st + TILE_B;
        const uint32_t bH = st + 2 * TILE_B, bL = st + 3 * TILE_B;

#pragma unroll
        for (int ks = 0; ks < 4; ks++) {
            const uint32_t kb = (uint32_t)ks * 32;   // 16 bf16 = 32B
            uint32_t ah[2][4], al[2][4];
#pragma unroll
            for (int sub = 0; sub < 2; sub++) {
                uint32_t off = swz128(aOffBase + (uint32_t)sub * 16 * 128 + kb);
                LDSM4(ah[sub], aH + off);
                LDSM4(al[sub], aL + off);
            }
#pragma unroll
            for (int nb = 0; nb < 4; nb++) {
                uint32_t off = swz128(bOffBase + (uint32_t)nb * 16 * 128 + kb);
                uint32_t bh[4], bl[4];
                LDSM4(bh, bH + off);
                LDSM4(bl, bL + off);
#pragma unroll
                for (int sub = 0; sub < 2; sub++) {
                    MMA16816(acc[sub][nb * 2],     ah[sub], bh[0], bh[1]);
                    MMA16816(acc[sub][nb * 2],     ah[sub], bl[0], bl[1]);
                    MMA16816(acc[sub][nb * 2],     al[sub], bh[0], bh[1]);
                    MMA16816(acc[sub][nb * 2 + 1], ah[sub], bh[2], bh[3]);
                    MMA16816(acc[sub][nb * 2 + 1], ah[sub], bl[2], bl[3]);
                    MMA16816(acc[sub][nb * 2 + 1], al[sub], bh[2], bh[3]);
                }
            }
        }
        __syncwarp();
        if (lane == 0) MBARRIER_ARRIVE(emt0 + 8 * s);

        // refill this stage for k-iter i+GS once all warps released it
        if (i + GS < GNK && tid == 0) {
            MBARRIER_WAIT_PARITY(emt0 + 8 * s, ph);
            MBARRIER_EXPECT_TX(full0 + 8 * s, STAGE_B);
            int k0 = (i + GS) * GBK;
            tma2d(st,              &tmAh, k0, bm, full0 + 8 * s);
            tma2d(st + TILE_B,     &tmAl, k0, bm, full0 + 8 * s);
            tma2d(st + 2 * TILE_B, &tmBh, k0, bn, full0 + 8 * s);
            tma2d(st + 3 * TILE_B, &tmBl, k0, bn, full0 + 8 * s);
        }
    }

    // ---- epilogue: registers -> global with bias ----
    const int r0 = bm + wm * 32 + (lane >> 2);
    const int c0 = bn + wn * 64 + (lane & 3) * 2;
#pragma unroll
    for (int sub = 0; sub < 2; sub++) {
#pragma unroll
        for (int nb = 0; nb < 8; nb++) {
            int row = r0 + sub * 16;
            int col = c0 + nb * 8;
            float2 bv = *(const float2*)(bias + col);
            float2 o0 = make_float2(acc[sub][nb][0] + bv.x, acc[sub][nb][1] + bv.y);
            float2 o1 = make_float2(acc[sub][nb][2] + bv.x, acc[sub][nb][3] + bv.y);
            *(float2*)(C + (size_t)row * GN + col)       = o0;
            *(float2*)(C + (size_t)(row + 8) * GN + col) = o1;
        }
    }
}

// ===================================================================
// Causal flash attention, fp32 (unchanged — R4 target).
// ===================================================================
#define FS 68

__global__ __launch_bounds__(256)
void flash_attn(const float* __restrict__ Q, const float* __restrict__ K,
                const float* __restrict__ V, float* __restrict__ O)
{
    extern __shared__ __align__(16) float smem[];
    float* Qs = smem;
    float* Ks = smem + 64 * FS;
    float* Vs = smem + 2 * 64 * FS;
    float* Ps = smem + 3 * 64 * FS;

    const int tid   = threadIdx.x;
    const int warp  = tid >> 5;
    const int lane  = tid & 31;
    const int qtile = blockIdx.x;
    const int h     = blockIdx.y;
    const int b     = blockIdx.z;
    const int q0    = qtile * 64;
    const int rbase = warp * 8;
    const size_t headoff = (size_t)h * HDIM;

#pragma unroll
    for (int i = 0; i < 4; i++) {
        int e = tid + i * 256;
        int r = e >> 4;
        int c = (e & 15) * 4;
        float4 v = *(const float4*)(Q + (size_t)(b * SEQ + q0 + r) * EMBED + headoff + c);
        v.x *= 0.125f; v.y *= 0.125f; v.z *= 0.125f; v.w *= 0.125f;
        *(float4*)&Qs[r * FS + c] = v;
    }

    float m[8], l[8], o0[8], o1[8];
#pragma unroll
    for (int rr = 0; rr < 8; rr++) { m[rr] = -1e30f; l[rr] = 0.0f; o0[rr] = 0.0f; o1[rr] = 0.0f; }

    for (int kt = 0; kt <= qtile; kt++) {
        __syncthreads();
        const int kbase = kt * 64;
#pragma unroll
        for (int i = 0; i < 4; i++) {
            int e = tid + i * 256;
            int r = e >> 4;
            int c = (e & 15) * 4;
            size_t g = (size_t)(b * SEQ + kbase + r) * EMBED + headoff + c;
            *(float4*)&Ks[r * FS + c] = *(const float4*)(K + g);
            *(float4*)&Vs[r * FS + c] = *(const float4*)(V + g);
        }
        __syncthreads();

#pragma unroll
        for (int rr = 0; rr < 8; rr++) {
            const float* qrow = &Qs[(rbase + rr) * FS];
            const float* k0p  = &Ks[lane * FS];
            const float* k1p  = &Ks[(lane + 32) * FS];
            ull s0a = 0ull, s0b = 0ull, s1a = 0ull, s1b = 0ull;
#pragma unroll
            for (int d = 0; d < 64; d += 4) {
                float4 q  = *(const float4*)(qrow + d);
                float4 ka = *(const float4*)(k0p + d);
                float4 kb = *(const float4*)(k1p + d);
                ull qlo = pk(q.x, q.y), qhi = pk(q.z, q.w);
                fma2(s0a, qlo, pk(ka.x, ka.y));
                fma2(s0b, qhi, pk(ka.z, ka.w));
                fma2(s1a, qlo, pk(kb.x, kb.y));
                fma2(s1b, qhi, pk(kb.z, kb.w));
            }
            float2 u;
            u = upk(s0a); float s0 = u.x + u.y; u = upk(s0b); s0 += u.x + u.y;
            u = upk(s1a); float s1 = u.x + u.y; u = upk(s1b); s1 += u.x + u.y;

            const int qg = q0 + rbase + rr;
            if (kbase + lane      > qg) s0 = -1e30f;
            if (kbase + lane + 32 > qg) s1 = -1e30f;

            float mx = fmaxf(s0, s1);
#pragma unroll
            for (int off = 16; off > 0; off >>= 1)
                mx = fmaxf(mx, __shfl_xor_sync(0xffffffffu, mx, off));
            float mnew = fmaxf(m[rr], mx);
            float corr = __expf(m[rr] - mnew);
            float p0 = __expf(s0 - mnew);
            float p1 = __expf(s1 - mnew);
            float ps = p0 + p1;
#pragma unroll
            for (int off = 16; off > 0; off >>= 1)
                ps += __shfl_xor_sync(0xffffffffu, ps, off);
            l[rr] = l[rr] * corr + ps;
            o0[rr] *= corr; o1[rr] *= corr;
            m[rr] = mnew;
            Ps[(rbase + rr) * FS + lane]      = p0;
            Ps[(rbase + rr) * FS + lane + 32] = p1;
        }
        __syncwarp();

#pragma unroll 4
        for (int c = 0; c < 64; c++) {
            float2 v = *(const float2*)&Vs[c * FS + 2 * lane];
#pragma unroll
            for (int rr = 0; rr < 8; rr++) {
                float p = Ps[(rbase + rr) * FS + c];
                o0[rr] += p * v.x;
                o1[rr] += p * v.y;
            }
        }
        __syncwarp();
    }

#pragma unroll
    for (int rr = 0; rr < 8; rr++) {
        float inv = 1.0f / l[rr];
        float2 o = make_float2(o0[rr] * inv, o1[rr] * inv);
        *(float2*)(O + (size_t)(b * SEQ + q0 + rbase + rr) * EMBED + headoff + 2 * lane) = o;
    }
}

// ===================================================================
// host: tensormap building + launch sequence
// ===================================================================
typedef CUresult (*PFN_tmap)(CUtensorMap*, CUtensorMapDataType, cuuint32_t, void*,
                             const cuuint64_t*, const cuuint64_t*, const cuuint32_t*,
                             const cuuint32_t*, CUtensorMapInterleave, CUtensorMapSwizzle,
                             CUtensorMapL2promotion, CUtensorMapFloatOOBfill);

static void make_map2d(PFN_tmap fn, CUtensorMap* m, void* base, int rows) {
    cuuint64_t dims[2]    = {(cuuint64_t)GK, (cuuint64_t)rows};
    cuuint64_t strides[1] = {(cuuint64_t)GK * 2};
    cuuint32_t box[2]     = {64u, 128u};
    cuuint32_t estr[2]    = {1u, 1u};
    fn(m, CU_TENSOR_MAP_DATA_TYPE_BFLOAT16, 2, base, dims, strides, box, estr,
       CU_TENSOR_MAP_INTERLEAVE_NONE, CU_TENSOR_MAP_SWIZZLE_128B,
       CU_TENSOR_MAP_L2_PROMOTION_L2_128B, CU_TENSOR_MAP_FLOAT_OOB_FILL_NONE);
}

extern "C" void kernel_launch(void* const* d_in, const int* in_sizes, int n_in,
                              void* d_out, int out_size)
{
    (void)in_sizes; (void)n_in; (void)out_size;
    const float* query = (const float*)d_in[0];
    const float* key   = (const float*)d_in[1];
    const float* value = (const float*)d_in[2];
    // d_in[3]: causal mask — analytically tril, applied in-kernel.
    const float* Wq = (const float*)d_in[4];
    const float* bq = (const float*)d_in[5];
    const float* Wk = (const float*)d_in[6];
    const float* bk = (const float*)d_in[7];
    const float* Wv = (const float*)d_in[8];
    const float* bv = (const float*)d_in[9];
    const float* Wo = (const float*)d_in[10];
    const float* bo = (const float*)d_in[11];
    float* out = (float*)d_out;

    float *pQ, *pK, *pV, *pC;
    __nv_bfloat16 *pAh, *pAl, *pWh, *pWl;
    cudaGetSymbolAddress((void**)&pQ, g_Q);
    cudaGetSymbolAddress((void**)&pK, g_K);
    cudaGetSymbolAddress((void**)&pV, g_V);
    cudaGetSymbolAddress((void**)&pC, g_Ctx);
    cudaGetSymbolAddress((void**)&pAh, g_Ah);
    cudaGetSymbolAddress((void**)&pAl, g_Al);
    cudaGetSymbolAddress((void**)&pWh, g_Wh);
    cudaGetSymbolAddress((void**)&pWl, g_Wl);

    static PFN_tmap pfn = nullptr;
    if (!pfn) {
        cudaDriverEntryPointQueryResult st;
        cudaGetDriverEntryPointByVersion("cuTensorMapEncodeTiled", (void**)&pfn,
                                         12000, cudaEnableDefault, &st);
    }
    CUtensorMap mAh, mAl, mWh, mWl;
    make_map2d(pfn, &mAh, pAh, NTOK);
    make_map2d(pfn, &mAl, pAl, NTOK);
    make_map2d(pfn, &mWh, pWh, EMBED);
    make_map2d(pfn, &mWl, pWl, EMBED);

    static bool attr_done = false;
    if (!attr_done) {
        cudaFuncSetAttribute(gemm_bf16x3, cudaFuncAttributeMaxDynamicSharedMemorySize, GEMM_SMEM);
        cudaFuncSetAttribute(flash_attn, cudaFuncAttributeMaxDynamicSharedMemorySize,
                             4 * 64 * FS * (int)sizeof(float));
        attr_done = true;
    }

    const int actBlocks = (NTOK * EMBED) / (256 * 4);   // 4096
    const int wBlocks   = (EMBED * EMBED) / (256 * 4);  // 1024
    dim3 gg(GN / 128, NTOK / 128);                      // (8, 32)

    split_bf16<<<actBlocks, 256>>>(query, pAh, pAl);
    split_bf16<<<wBlocks, 256>>>(Wq, pWh, pWl);
    gemm_bf16x3<<<gg, 256, GEMM_SMEM>>>(mAh, mAl, mWh, mWl, bq, pQ);

    split_bf16<<<actBlocks, 256>>>(key, pAh, pAl);
    split_bf16<<<wBlocks, 256>>>(Wk, pWh, pWl);
    gemm_bf16x3<<<gg, 256, GEMM_SMEM>>>(mAh, mAl, mWh, mWl, bk, pK);

    split_bf16<<<actBlocks, 256>>>(value, pAh, pAl);
    split_bf16<<<wBlocks, 256>>>(Wv, pWh, pWl);
    gemm_bf16x3<<<gg, 256, GEMM_SMEM>>>(mAh, mAl, mWh, mWl, bv, pV);

    dim3 ga(SEQ / 64, HEADS, BSZ);
    flash_attn<<<ga, 256, 4 * 64 * FS * (int)sizeof(float)>>>(pQ, pK, pV, pC);

    split_bf16<<<actBlocks, 256>>>(pC, pAh, pAl);
    split_bf16<<<wBlocks, 256>>>(Wo, pWh, pWl);
    gemm_bf16x3<<<gg, 256, GEMM_SMEM>>>(mAh, mAl, mWh, mWl, bo, out);
}

// round 4
// speedup vs baseline: 3.8243x; 2.1708x over previous
#include <cuda_runtime.h>
#include <cuda.h>
#include <cuda_bf16.h>
#include <cstdint>

typedef unsigned long long ull;

#define BSZ    2
#define SEQ    2048
#define EMBED  1024
#define HEADS  16
#define HDIM   64
#define NTOK   (BSZ*SEQ)

// ---------------- scratch (no allocations allowed) ----------------
__device__ __nv_bfloat16 g_Qh[NTOK*EMBED];
__device__ __nv_bfloat16 g_Ql[NTOK*EMBED];
__device__ __nv_bfloat16 g_Kh[NTOK*EMBED];
__device__ __nv_bfloat16 g_Kl[NTOK*EMBED];
__device__ __nv_bfloat16 g_Vh[NTOK*EMBED];
__device__ __nv_bfloat16 g_Vl[NTOK*EMBED];
__device__ __nv_bfloat16 g_Ah[NTOK*EMBED];   // activation / ctx hi
__device__ __nv_bfloat16 g_Al[NTOK*EMBED];   // activation / ctx lo
__device__ __nv_bfloat16 g_Wh[EMBED*EMBED];
__device__ __nv_bfloat16 g_Wl[EMBED*EMBED];

// ---------------- PTX helpers (all non-'a' features) ---------------
__device__ __forceinline__ uint32_t smem_u32(const void* p) {
    uint32_t a;
    asm("{ .reg .u64 t; cvta.to.shared.u64 t, %1; cvt.u32.u64 %0, t; }" : "=r"(a) : "l"(p));
    return a;
}

#define MBARRIER_INIT(mbar, cnt) \
    asm volatile("mbarrier.init.shared.b64 [%0], %1;" :: "r"(mbar), "r"(cnt) : "memory")
#define MBARRIER_EXPECT_TX(mbar, bytes) \
    asm volatile("mbarrier.arrive.expect_tx.shared.b64 _, [%0], %1;" :: "r"(mbar), "r"(bytes) : "memory")
#define MBARRIER_ARRIVE(mbar) \
    asm volatile("mbarrier.arrive.release.cta.shared.b64 _, [%0];" :: "r"(mbar) : "memory")

#define MBARRIER_WAIT_PARITY(mbar_addr, phase_parity) do {                                   \
    uint32_t _mbar = (uint32_t)(mbar_addr);                                                  \
    uint32_t _par  = (uint32_t)(phase_parity);                                               \
    uint32_t _done;                                                                          \
    asm volatile("{\n\t.reg .pred p;\n\t"                                                    \
        "mbarrier.try_wait.parity.acquire.cta.shared::cta.b64 p, [%1], %2;\n\t"              \
        "selp.b32 %0, 1, 0, p;\n\t}"                                                         \
        : "=r"(_done) : "r"(_mbar), "r"(_par) : "memory");                                   \
    if (!_done) {                                                                            \
        asm volatile("{\n\t.reg .pred P1;\n\t"                                               \
            "WL_%=:\n\t"                                                                     \
            "mbarrier.try_wait.parity.acquire.cta.shared::cta.b64 P1, [%0], %1, 0x989680;\n\t" \
            "@P1 bra.uni WD_%=;\n\t"                                                         \
            "bra.uni WL_%=;\n\t"                                                             \
            "WD_%=:\n\t}"                                                                    \
            :: "r"(_mbar), "r"(_par) : "memory");                                            \
    }                                                                                        \
} while (0)

__device__ __forceinline__ void tma2d(uint32_t dst, const CUtensorMap* map,
                                      int x, int y, uint32_t mbar) {
    asm volatile(
        "cp.async.bulk.tensor.2d.shared::cta.global.tile.mbarrier::complete_tx::bytes "
        "[%0], [%1, {%2, %3}], [%4];"
        :: "r"(dst), "l"(map), "r"(x), "r"(y), "r"(mbar) : "memory");
}

#define LDSM4(r, addr)                                                           \
    asm volatile("ldmatrix.sync.aligned.m8n8.x4.shared.b16 {%0,%1,%2,%3}, [%4];" \
        : "=r"((r)[0]), "=r"((r)[1]), "=r"((r)[2]), "=r"((r)[3]) : "r"(addr))

#define LDSM4T(r, addr)                                                          \
    asm volatile("ldmatrix.sync.aligned.m8n8.x4.trans.shared.b16 {%0,%1,%2,%3}, [%4];" \
        : "=r"((r)[0]), "=r"((r)[1]), "=r"((r)[2]), "=r"((r)[3]) : "r"(addr))

#define MMA16816(d, a, b0v, b1v)                                                 \
    asm volatile("mma.sync.aligned.m16n8k16.row.col.f32.bf16.bf16.f32 "          \
        "{%0,%1,%2,%3}, {%4,%5,%6,%7}, {%8,%9}, {%0,%1,%2,%3};"                  \
        : "+f"((d)[0]), "+f"((d)[1]), "+f"((d)[2]), "+f"((d)[3])                 \
        : "r"((a)[0]), "r"((a)[1]), "r"((a)[2]), "r"((a)[3]), "r"(b0v), "r"(b1v))

__device__ __forceinline__ uint32_t swz128(uint32_t o) {  // Swizzle<3,4,3>
    return o ^ ((o >> 3) & 0x70u);
}
__device__ __forceinline__ float ex2f(float x) {
    float y; asm("ex2.approx.ftz.f32 %0, %1;" : "=f"(y) : "f"(x)); return y;
}
__device__ __forceinline__ uint32_t prmt7632(uint32_t a, uint32_t b) {
    uint32_t d; asm("prmt.b32 %0, %1, %2, 0x7632;" : "=r"(d) : "r"(a), "r"(b)); return d;
}
__device__ __forceinline__ uint32_t cvt_bf16x2(float hi, float lo) {
    uint32_t d; asm("cvt.rn.bf16x2.f32 %0, %1, %2;" : "=r"(d) : "f"(hi), "f"(lo)); return d;
}
__device__ __forceinline__ float truncbf(float x) {
    return __uint_as_float(__float_as_uint(x) & 0xffff0000u);
}

// ===================================================================
// split: fp32 -> bf16 hi + bf16 lo
// ===================================================================
__global__ __launch_bounds__(256)
void split_bf16(const float* __restrict__ x, __nv_bfloat16* __restrict__ hi,
                __nv_bfloat16* __restrict__ lo)
{
    int i = (blockIdx.x * 256 + threadIdx.x) * 4;
    float4 v = *(const float4*)(x + i);
    __nv_bfloat16 h0 = __float2bfloat16_rn(v.x);
    __nv_bfloat16 h1 = __float2bfloat16_rn(v.y);
    __nv_bfloat16 h2 = __float2bfloat16_rn(v.z);
    __nv_bfloat16 h3 = __float2bfloat16_rn(v.w);
    __nv_bfloat16 l0 = __float2bfloat16_rn(v.x - __bfloat162float(h0));
    __nv_bfloat16 l1 = __float2bfloat16_rn(v.y - __bfloat162float(h1));
    __nv_bfloat16 l2 = __float2bfloat16_rn(v.z - __bfloat162float(h2));
    __nv_bfloat16 l3 = __float2bfloat16_rn(v.w - __bfloat162float(h3));
    ushort4 hv = make_ushort4(*(unsigned short*)&h0, *(unsigned short*)&h1,
                              *(unsigned short*)&h2, *(unsigned short*)&h3);
    ushort4 lv = make_ushort4(*(unsigned short*)&l0, *(unsigned short*)&l1,
                              *(unsigned short*)&l2, *(unsigned short*)&l3);
    *(ushort4*)(hi + i) = hv;
    *(ushort4*)(lo + i) = lv;
}

// ===================================================================
// bf16x3 GEMM (NT): 4096x1024x1024. Epilogue: fp32 OR bf16 hi/lo.
// ===================================================================
#define GK      1024
#define GN      1024
#define GBK     64
#define GNK     (GK/GBK)
#define GS      3
#define TILE_B  16384
#define STAGE_B (4*TILE_B)
#define GEMM_SMEM (GS*STAGE_B + 1024)

__global__ __launch_bounds__(256)
void gemm_bf16x3(const __grid_constant__ CUtensorMap tmAh,
                 const __grid_constant__ CUtensorMap tmAl,
                 const __grid_constant__ CUtensorMap tmBh,
                 const __grid_constant__ CUtensorMap tmBl,
                 const float* __restrict__ bias,
                 float* __restrict__ Cf,
                 __nv_bfloat16* __restrict__ Ch, __nv_bfloat16* __restrict__ Cl)
{
    extern __shared__ uint8_t dsm[];
    __shared__ __align__(8) ull s_mbar[2 * GS];

    const int tid  = threadIdx.x;
    const int wid  = tid >> 5;
    const int lane = tid & 31;
    const int wm   = wid & 3;
    const int wn   = wid >> 2;
    const int bm   = blockIdx.y * 128;
    const int bn   = blockIdx.x * 128;

    const uint32_t tile0 = (smem_u32(dsm) + 1023u) & ~1023u;
    const uint32_t mb    = smem_u32(s_mbar);
    const uint32_t full0 = mb;
    const uint32_t emt0  = mb + 8 * GS;

    if (tid == 0) {
        for (int s = 0; s < GS; s++) {
            MBARRIER_INIT(full0 + 8 * s, 1);
            MBARRIER_INIT(emt0 + 8 * s, 8);
        }
    }
    __syncthreads();

    if (tid == 0) {
#pragma unroll
        for (int s = 0; s < GS; s++) {
            uint32_t st = tile0 + s * STAGE_B;
            MBARRIER_EXPECT_TX(full0 + 8 * s, STAGE_B);
            int k0 = s * GBK;
            tma2d(st,              &tmAh, k0, bm, full0 + 8 * s);
            tma2d(st + TILE_B,     &tmAl, k0, bm, full0 + 8 * s);
            tma2d(st + 2 * TILE_B, &tmBh, k0, bn, full0 + 8 * s);
            tma2d(st + 3 * TILE_B, &tmBl, k0, bn, full0 + 8 * s);
        }
    }

    float acc[2][8][4];
#pragma unroll
    for (int i = 0; i < 2; i++)
#pragma unroll
        for (int j = 0; j < 8; j++)
#pragma unroll
            for (int q = 0; q < 4; q++) acc[i][j][q] = 0.0f;

    const int aRow = wm * 32 + (lane & 7) + ((lane >> 3) & 1) * 8;
    const uint32_t aOffBase = (uint32_t)aRow * 128 + ((lane >> 4) & 1) * 16;
    const int bRow = wn * 64 + (lane & 7) + ((lane >> 4) & 1) * 8;
    const uint32_t bOffBase = (uint32_t)bRow * 128 + ((lane >> 3) & 1) * 16;

    for (int i = 0; i < GNK; i++) {
        const int s  = i % GS;
        const int ph = (i / GS) & 1;
        MBARRIER_WAIT_PARITY(full0 + 8 * s, ph);

        const uint32_t st  = tile0 + s * STAGE_B;
        const uint32_t aH = st, aL = st + TILE_B;
        const uint32_t bH = st + 2 * TILE_B, bL = st + 3 * TILE_B;

#pragma unroll
        for (int ks = 0; ks < 4; ks++) {
            const uint32_t kb = (uint32_t)ks * 32;
            uint32_t ah[2][4], al[2][4];
#pragma unroll
            for (int sub = 0; sub < 2; sub++) {
                uint32_t off = swz128(aOffBase + (uint32_t)sub * 16 * 128 + kb);
                LDSM4(ah[sub], aH + off);
                LDSM4(al[sub], aL + off);
            }
#pragma unroll
            for (int nb = 0; nb < 4; nb++) {
                uint32_t off = swz128(bOffBase + (uint32_t)nb * 16 * 128 + kb);
                uint32_t bh[4], bl[4];
                LDSM4(bh, bH + off);
                LDSM4(bl, bL + off);
#pragma unroll
                for (int sub = 0; sub < 2; sub++) {
                    MMA16816(acc[sub][nb * 2],     ah[sub], bh[0], bh[1]);
                    MMA16816(acc[sub][nb * 2 + 1], ah[sub], bh[2], bh[3]);
                    MMA16816(acc[sub][nb * 2],     ah[sub], bl[0], bl[1]);
                    MMA16816(acc[sub][nb * 2 + 1], ah[sub], bl[2], bl[3]);
                    MMA16816(acc[sub][nb * 2],     al[sub], bh[0], bh[1]);
                    MMA16816(acc[sub][nb * 2 + 1], al[sub], bh[2], bh[3]);
                }
            }
        }
        __syncwarp();
        if (lane == 0) MBARRIER_ARRIVE(emt0 + 8 * s);

        if (i + GS < GNK && tid == 0) {
            MBARRIER_WAIT_PARITY(emt0 + 8 * s, ph);
            MBARRIER_EXPECT_TX(full0 + 8 * s, STAGE_B);
            int k0 = (i + GS) * GBK;
            tma2d(st,              &tmAh, k0, bm, full0 + 8 * s);
            tma2d(st + TILE_B,     &tmAl, k0, bm, full0 + 8 * s);
            tma2d(st + 2 * TILE_B, &tmBh, k0, bn, full0 + 8 * s);
            tma2d(st + 3 * TILE_B, &tmBl, k0, bn, full0 + 8 * s);
        }
    }

    // ---- epilogue ----
    const int r0 = bm + wm * 32 + (lane >> 2);
    const int c0 = bn + wn * 64 + (lane & 3) * 2;
#pragma unroll
    for (int sub = 0; sub < 2; sub++) {
#pragma unroll
        for (int nb = 0; nb < 8; nb++) {
            int row = r0 + sub * 16;
            int col = c0 + nb * 8;
            float2 bv = *(const float2*)(bias + col);
            float o0x = acc[sub][nb][0] + bv.x, o0y = acc[sub][nb][1] + bv.y;
            float o1x = acc[sub][nb][2] + bv.x, o1y = acc[sub][nb][3] + bv.y;
            if (Cf) {
                *(float2*)(Cf + (size_t)row * GN + col)       = make_float2(o0x, o0y);
                *(float2*)(Cf + (size_t)(row + 8) * GN + col) = make_float2(o1x, o1y);
            } else {
                uint32_t h0 = prmt7632(__float_as_uint(o0x), __float_as_uint(o0y));
                uint32_t l0 = cvt_bf16x2(o0y - truncbf(o0y), o0x - truncbf(o0x));
                uint32_t h1 = prmt7632(__float_as_uint(o1x), __float_as_uint(o1y));
                uint32_t l1 = cvt_bf16x2(o1y - truncbf(o1y), o1x - truncbf(o1x));
                *(uint32_t*)(Ch + (size_t)row * GN + col)       = h0;
                *(uint32_t*)(Cl + (size_t)row * GN + col)       = l0;
                *(uint32_t*)(Ch + (size_t)(row + 8) * GN + col) = h1;
                *(uint32_t*)(Cl + (size_t)(row + 8) * GN + col) = l1;
            }
        }
    }
}

// ===================================================================
// Causal flash attention via mma.sync, bf16x3 compensated.
// CTA: 128 queries x one (b,h). 8 warps x m16 rows. 128-key tiles.
// ===================================================================
#define FSTG 3
#define FT_B 16384
#define FST_B (4*FT_B)
#define FLASH_SMEM (FSTG*FST_B + 1024)
#define C1F 0.18033688011112042f   // log2(e)/8

__global__ __launch_bounds__(256)
void flash_mma(const __grid_constant__ CUtensorMap tmQh,
               const __grid_constant__ CUtensorMap tmQl,
               const __grid_constant__ CUtensorMap tmKh,
               const __grid_constant__ CUtensorMap tmKl,
               const __grid_constant__ CUtensorMap tmVh,
               const __grid_constant__ CUtensorMap tmVl,
               __nv_bfloat16* __restrict__ Oh, __nv_bfloat16* __restrict__ Ol)
{
    extern __shared__ uint8_t dsm[];
    __shared__ __align__(8) ull s_mbar[2 * FSTG + 1];

    const int tid  = threadIdx.x;
    const int wid  = tid >> 5;
    const int lane = tid & 31;
    const int qt   = (int)gridDim.x - 1 - (int)blockIdx.x;  // heavy CTAs first
    const int h    = blockIdx.y;
    const int b    = blockIdx.z;
    const int q0   = qt * 128;
    const int nkt  = qt + 1;
    const int xoff = h * HDIM;
    const int yb   = b * SEQ;

    const uint32_t tile0 = (smem_u32(dsm) + 1023u) & ~1023u;
    const uint32_t mb    = smem_u32(s_mbar);
    const uint32_t full0 = mb;
    const uint32_t emt0  = mb + 8 * FSTG;
    const uint32_t qbar  = mb + 16 * FSTG;

    if (tid == 0) {
        for (int s = 0; s < FSTG; s++) {
            MBARRIER_INIT(full0 + 8 * s, 1);
            MBARRIER_INIT(emt0 + 8 * s, 8);
        }
        MBARRIER_INIT(qbar, 1);
        MBARRIER_EXPECT_TX(qbar, 2 * FT_B);
        tma2d(tile0,        &tmQh, xoff, yb + q0, qbar);
        tma2d(tile0 + FT_B, &tmQl, xoff, yb + q0, qbar);
    }
    __syncthreads();
    MBARRIER_WAIT_PARITY(qbar, 0);

    // Q fragments (persist in registers)
    const uint32_t aOff = (uint32_t)(wid * 16 + (lane & 7) + ((lane >> 3) & 1) * 8) * 128
                        + ((lane >> 4) & 1) * 16;
    uint32_t qh[4][4], ql[4][4];
#pragma unroll
    for (int kb = 0; kb < 4; kb++) {
        uint32_t off = swz128(aOff + kb * 32);
        LDSM4(qh[kb], tile0 + off);
        LDSM4(ql[kb], tile0 + FT_B + off);
    }
    __syncthreads();   // Q reads done before K/V TMA reuses stage 0

    if (tid == 0) {
        int npre = nkt < FSTG ? nkt : FSTG;
        for (int p = 0; p < npre; p++) {
            uint32_t st = tile0 + p * FST_B;
            MBARRIER_EXPECT_TX(full0 + 8 * p, FST_B);
            int y = yb + p * 128;
            tma2d(st,            &tmKh, xoff, y, full0 + 8 * p);
            tma2d(st + FT_B,     &tmKl, xoff, y, full0 + 8 * p);
            tma2d(st + 2 * FT_B, &tmVh, xoff, y, full0 + 8 * p);
            tma2d(st + 3 * FT_B, &tmVl, xoff, y, full0 + 8 * p);
        }
    }

    float m0 = -1e30f, m1 = -1e30f, l0 = 0.0f, l1 = 0.0f;
    float oacc[8][4];
#pragma unroll
    for (int i = 0; i < 8; i++)
#pragma unroll
        for (int j = 0; j < 4; j++) oacc[i][j] = 0.0f;

    const uint32_t kOff = (uint32_t)((lane & 7) + ((lane >> 4) & 1) * 8) * 128
                        + ((lane >> 3) & 1) * 16;
    const uint32_t vOff = (uint32_t)((lane & 7) + ((lane >> 3) & 1) * 8) * 128
                        + ((lane >> 4) & 1) * 16;
    const int qrow = wid * 16 + (lane >> 2);   // local query row (of row pair)

    for (int kt = 0; kt < nkt; kt++) {
        const int s  = kt % FSTG;
        const int ph = (kt / FSTG) & 1;
        MBARRIER_WAIT_PARITY(full0 + 8 * s, ph);
        const uint32_t stb = tile0 + s * FST_B;

        // ---- S = Q K^T, 3-pass compensated ----
        float sc[16][4];
#pragma unroll
        for (int i = 0; i < 16; i++)
#pragma unroll
            for (int j = 0; j < 4; j++) sc[i][j] = 0.0f;

#pragma unroll
        for (int kb = 0; kb < 4; kb++) {
#pragma unroll
            for (int nb2 = 0; nb2 < 8; nb2++) {
                uint32_t off = swz128(kOff + (uint32_t)nb2 * 2048 + (uint32_t)kb * 32);
                uint32_t bh[4], bl[4];
                LDSM4(bh, stb + off);
                LDSM4(bl, stb + FT_B + off);
                MMA16816(sc[2 * nb2],     qh[kb], bh[0], bh[1]);
                MMA16816(sc[2 * nb2 + 1], qh[kb], bh[2], bh[3]);
                MMA16816(sc[2 * nb2],     qh[kb], bl[0], bl[1]);
                MMA16816(sc[2 * nb2 + 1], qh[kb], bl[2], bl[3]);
                MMA16816(sc[2 * nb2],     ql[kb], bh[0], bh[1]);
                MMA16816(sc[2 * nb2 + 1], ql[kb], bh[2], bh[3]);
            }
        }

        // scale into exp2 domain
#pragma unroll
        for (int nb = 0; nb < 16; nb++)
#pragma unroll
            for (int j = 0; j < 4; j++) sc[nb][j] *= C1F;

        // causal mask on diagonal tile
        if (kt == qt) {
#pragma unroll
            for (int nb = 0; nb < 16; nb++) {
                int c = nb * 8 + (lane & 3) * 2;
                if (c     > qrow)     sc[nb][0] = -1e30f;
                if (c + 1 > qrow)     sc[nb][1] = -1e30f;
                if (c     > qrow + 8) sc[nb][2] = -1e30f;
                if (c + 1 > qrow + 8) sc[nb][3] = -1e30f;
            }
        }

        // ---- online softmax (rows r, r+8 per lane) ----
        float mx0 = -1e30f, mx1 = -1e30f;
#pragma unroll
        for (int nb = 0; nb < 16; nb++) {
            mx0 = fmaxf(mx0, fmaxf(sc[nb][0], sc[nb][1]));
            mx1 = fmaxf(mx1, fmaxf(sc[nb][2], sc[nb][3]));
        }
        mx0 = fmaxf(mx0, __shfl_xor_sync(0xffffffffu, mx0, 1));
        mx0 = fmaxf(mx0, __shfl_xor_sync(0xffffffffu, mx0, 2));
        mx1 = fmaxf(mx1, __shfl_xor_sync(0xffffffffu, mx1, 1));
        mx1 = fmaxf(mx1, __shfl_xor_sync(0xffffffffu, mx1, 2));
        float mn0 = fmaxf(m0, mx0), mn1 = fmaxf(m1, mx1);
        float cor0 = ex2f(m0 - mn0), cor1 = ex2f(m1 - mn1);
        m0 = mn0; m1 = mn1;
        float su0 = 0.0f, su1 = 0.0f;
#pragma unroll
        for (int nb = 0; nb < 16; nb++) {
            sc[nb][0] = ex2f(sc[nb][0] - mn0); su0 += sc[nb][0];
            sc[nb][1] = ex2f(sc[nb][1] - mn0); su0 += sc[nb][1];
            sc[nb][2] = ex2f(sc[nb][2] - mn1); su1 += sc[nb][2];
            sc[nb][3] = ex2f(sc[nb][3] - mn1); su1 += sc[nb][3];
        }
        su0 += __shfl_xor_sync(0xffffffffu, su0, 1);
        su0 += __shfl_xor_sync(0xffffffffu, su0, 2);
        su1 += __shfl_xor_sync(0xffffffffu, su1, 1);
        su1 += __shfl_xor_sync(0xffffffffu, su1, 2);
        l0 = l0 * cor0 + su0;
        l1 = l1 * cor1 + su1;
#pragma unroll
        for (int nb = 0; nb < 8; nb++) {
            oacc[nb][0] *= cor0; oacc[nb][1] *= cor0;
            oacc[nb][2] *= cor1; oacc[nb][3] *= cor1;
        }

        // ---- O += P V, 3-pass compensated (P stays in registers) ----
#pragma unroll
        for (int kb2 = 0; kb2 < 8; kb2++) {
            const float* p0 = sc[2 * kb2];
            const float* p1 = sc[2 * kb2 + 1];
            uint32_t aph[4], apl[4];
            aph[0] = prmt7632(__float_as_uint(p0[0]), __float_as_uint(p0[1]));
            aph[1] = prmt7632(__float_as_uint(p0[2]), __float_as_uint(p0[3]));
            aph[2] = prmt7632(__float_as_uint(p1[0]), __float_as_uint(p1[1]));
            aph[3] = prmt7632(__float_as_uint(p1[2]), __float_as_uint(p1[3]));
            apl[0] = cvt_bf16x2(p0[1] - truncbf(p0[1]), p0[0] - truncbf(p0[0]));
            apl[1] = cvt_bf16x2(p0[3] - truncbf(p0[3]), p0[2] - truncbf(p0[2]));
            apl[2] = cvt_bf16x2(p1[1] - truncbf(p1[1]), p1[0] - truncbf(p1[0]));
            apl[3] = cvt_bf16x2(p1[3] - truncbf(p1[3]), p1[2] - truncbf(p1[2]));
#pragma unroll
            for (int db2 = 0; db2 < 4; db2++) {
                uint32_t off = swz128(vOff + (uint32_t)kb2 * 2048 + (uint32_t)db2 * 32);
                uint32_t vh[4], vl[4];
                LDSM4T(vh, stb + 2 * FT_B + off);
                LDSM4T(vl, stb + 3 * FT_B + off);
                MMA16816(oacc[2 * db2],     aph, vh[0], vh[1]);
                MMA16816(oacc[2 * db2 + 1], aph, vh[2], vh[3]);
                MMA16816(oacc[2 * db2],     aph, vl[0], vl[1]);
                MMA16816(oacc[2 * db2 + 1], aph, vl[2], vl[3]);
                MMA16816(oacc[2 * db2],     apl, vh[0], vh[1]);
                MMA16816(oacc[2 * db2 + 1], apl, vh[2], vh[3]);
            }
        }

        __syncwarp();
        if (lane == 0) MBARRIER_ARRIVE(emt0 + 8 * s);
        if (kt + FSTG < nkt && tid == 0) {
            MBARRIER_WAIT_PARITY(emt0 + 8 * s, ph);
            MBARRIER_EXPECT_TX(full0 + 8 * s, FST_B);
            int y = yb + (kt + FSTG) * 128;
            tma2d(stb,            &tmKh, xoff, y, full0 + 8 * s);
            tma2d(stb + FT_B,     &tmKl, xoff, y, full0 + 8 * s);
            tma2d(stb + 2 * FT_B, &tmVh, xoff, y, full0 + 8 * s);
            tma2d(stb + 3 * FT_B, &tmVl, xoff, y, full0 + 8 * s);
        }
    }

    // ---- epilogue: normalize, split to bf16 hi/lo, store ----
    float inv0 = 1.0f / l0, inv1 = 1.0f / l1;
    const size_t row0 = (size_t)(yb + q0 + wid * 16 + (lane >> 2));
    const int colb = xoff + (lane & 3) * 2;
#pragma unroll
    for (int nb = 0; nb < 8; nb++) {
        int c = colb + nb * 8;
        float a0 = oacc[nb][0] * inv0, a1 = oacc[nb][1] * inv0;
        float b0 = oacc[nb][2] * inv1, b1 = oacc[nb][3] * inv1;
        uint32_t h0 = prmt7632(__float_as_uint(a0), __float_as_uint(a1));
        uint32_t lo0 = cvt_bf16x2(a1 - truncbf(a1), a0 - truncbf(a0));
        uint32_t h1 = prmt7632(__float_as_uint(b0), __float_as_uint(b1));
        uint32_t lo1 = cvt_bf16x2(b1 - truncbf(b1), b0 - truncbf(b0));
        *(uint32_t*)(Oh + row0 * EMBED + c)       = h0;
        *(uint32_t*)(Ol + row0 * EMBED + c)       = lo0;
        *(uint32_t*)(Oh + (row0 + 8) * EMBED + c) = h1;
        *(uint32_t*)(Ol + (row0 + 8) * EMBED + c) = lo1;
    }
}

// ===================================================================
// host
// ===================================================================
typedef CUresult (*PFN_tmap)(CUtensorMap*, CUtensorMapDataType, cuuint32_t, void*,
                             const cuuint64_t*, const cuuint64_t*, const cuuint32_t*,
                             const cuuint32_t*, CUtensorMapInterleave, CUtensorMapSwizzle,
                             CUtensorMapL2promotion, CUtensorMapFloatOOBfill);

static void make_map2d(PFN_tmap fn, CUtensorMap* m, void* base, int rows) {
    cuuint64_t dims[2]    = {(cuuint64_t)EMBED, (cuuint64_t)rows};
    cuuint64_t strides[1] = {(cuuint64_t)EMBED * 2};
    cuuint32_t box[2]     = {64u, 128u};
    cuuint32_t estr[2]    = {1u, 1u};
    fn(m, CU_TENSOR_MAP_DATA_TYPE_BFLOAT16, 2, base, dims, strides, box, estr,
       CU_TENSOR_MAP_INTERLEAVE_NONE, CU_TENSOR_MAP_SWIZZLE_128B,
       CU_TENSOR_MAP_L2_PROMOTION_L2_128B, CU_TENSOR_MAP_FLOAT_OOB_FILL_NONE);
}

extern "C" void kernel_launch(void* const* d_in, const int* in_sizes, int n_in,
                              void* d_out, int out_size)
{
    (void)in_sizes; (void)n_in; (void)out_size;
    const float* query = (const float*)d_in[0];
    const float* key   = (const float*)d_in[1];
    const float* value = (const float*)d_in[2];
    // d_in[3]: causal mask — analytically tril, applied in-kernel.
    const float* Wq = (const float*)d_in[4];
    const float* bq = (const float*)d_in[5];
    const float* Wk = (const float*)d_in[6];
    const float* bk = (const float*)d_in[7];
    const float* Wv = (const float*)d_in[8];
    const float* bv = (const float*)d_in[9];
    const float* Wo = (const float*)d_in[10];
    const float* bo = (const float*)d_in[11];
    float* out = (float*)d_out;

    __nv_bfloat16 *pQh, *pQl, *pKh, *pKl, *pVh, *pVl, *pAh, *pAl, *pWh, *pWl;
    cudaGetSymbolAddress((void**)&pQh, g_Qh);
    cudaGetSymbolAddress((void**)&pQl, g_Ql);
    cudaGetSymbolAddress((void**)&pKh, g_Kh);
    cudaGetSymbolAddress((void**)&pKl, g_Kl);
    cudaGetSymbolAddress((void**)&pVh, g_Vh);
    cudaGetSymbolAddress((void**)&pVl, g_Vl);
    cudaGetSymbolAddress((void**)&pAh, g_Ah);
    cudaGetSymbolAddress((void**)&pAl, g_Al);
    cudaGetSymbolAddress((void**)&pWh, g_Wh);
    cudaGetSymbolAddress((void**)&pWl, g_Wl);

    static PFN_tmap pfn = nullptr;
    if (!pfn) {
        cudaDriverEntryPointQueryResult st;
        cudaGetDriverEntryPointByVersion("cuTensorMapEncodeTiled", (void**)&pfn,
                                         12000, cudaEnableDefault, &st);
    }
    CUtensorMap mAh, mAl, mWh, mWl, mQh, mQl, mKh, mKl, mVh, mVl;
    make_map2d(pfn, &mAh, pAh, NTOK);
    make_map2d(pfn, &mAl, pAl, NTOK);
    make_map2d(pfn, &mWh, pWh, EMBED);
    make_map2d(pfn, &mWl, pWl, EMBED);
    make_map2d(pfn, &mQh, pQh, NTOK);
    make_map2d(pfn, &mQl, pQl, NTOK);
    make_map2d(pfn, &mKh, pKh, NTOK);
    make_map2d(pfn, &mKl, pKl, NTOK);
    make_map2d(pfn, &mVh, pVh, NTOK);
    make_map2d(pfn, &mVl, pVl, NTOK);

    static bool attr_done = false;
    if (!attr_done) {
        cudaFuncSetAttribute(gemm_bf16x3, cudaFuncAttributeMaxDynamicSharedMemorySize, GEMM_SMEM);
        cudaFuncSetAttribute(flash_mma, cudaFuncAttributeMaxDynamicSharedMemorySize, FLASH_SMEM);
        attr_done = true;
    }

    const int actBlocks = (NTOK * EMBED) / (256 * 4);
    const int wBlocks   = (EMBED * EMBED) / (256 * 4);
    dim3 gg(GN / 128, NTOK / 128);

    split_bf16<<<actBlocks, 256>>>(query, pAh, pAl);
    split_bf16<<<wBlocks, 256>>>(Wq, pWh, pWl);
    gemm_bf16x3<<<gg, 256, GEMM_SMEM>>>(mAh, mAl, mWh, mWl, bq, nullptr, pQh, pQl);

    split_bf16<<<actBlocks, 256>>>(key, pAh, pAl);
    split_bf16<<<wBlocks, 256>>>(Wk, pWh, pWl);
    gemm_bf16x3<<<gg, 256, GEMM_SMEM>>>(mAh, mAl, mWh, mWl, bk, nullptr, pKh, pKl);

    split_bf16<<<actBlocks, 256>>>(value, pAh, pAl);
    split_bf16<<<wBlocks, 256>>>(Wv, pWh, pWl);
    gemm_bf16x3<<<gg, 256, GEMM_SMEM>>>(mAh, mAl, mWh, mWl, bv, nullptr, pVh, pVl);

    dim3 ga(SEQ / 128, HEADS, BSZ);
    flash_mma<<<ga, 256, FLASH_SMEM>>>(mQh, mQl, mKh, mKl, mVh, mVl, pAh, pAl);

    split_bf16<<<wBlocks, 256>>>(Wo, pWh, pWl);
    gemm_bf16x3<<<gg, 256, GEMM_SMEM>>>(mAh, mAl, mWh, mWl, bo, out, nullptr, nullptr);
}